// round 1
// baseline (speedup 1.0000x reference)
#include <cuda_runtime.h>
#include <cstdint>

// BiologicalWorkingMemory: B x (S=8 slots, D=64 dims) fused update.
// Layout: 8 lanes per batch (lane r holds elements [r*8, r*8+8) of every slot),
// 4 batches per warp, 256 threads/block -> 32 batches/block.

static __device__ __forceinline__ float gsum8(float v) {
    v += __shfl_xor_sync(0xffffffffu, v, 1);
    v += __shfl_xor_sync(0xffffffffu, v, 2);
    v += __shfl_xor_sync(0xffffffffu, v, 4);
    return v;
}

__global__ __launch_bounds__(256, 2) void wm_kernel(
    const float* __restrict__ mem,        // (B,8,64)
    const float* __restrict__ act_in,     // (B,8)
    const float* __restrict__ gate_in,    // (B,8)
    const float* __restrict__ thr_in,     // (B,8)
    const float* __restrict__ refresh_in, // (B,8)
    const float* __restrict__ intf,       // (B,8,8)
    const float* __restrict__ maint_in,   // (B,8)
    const float* __restrict__ x_in,       // (B,64)
    const float* __restrict__ gsig_in,    // (B,8)
    const float* __restrict__ rsig_in,    // (B,8)
    const void* __restrict__ dt_ptr,
    float* __restrict__ out,
    int B)
{
    const unsigned FULL = 0xffffffffu;
    const int lane = threadIdx.x & 31;
    const int warp = blockIdx.x * (blockDim.x >> 5) + (threadIdx.x >> 5);
    const int grp  = lane >> 3;   // group (batch within warp)
    const int r    = lane & 7;    // slot rank / element-chunk rank
    const int b    = warp * 4 + grp;
    const bool valid = (b < B);
    const int bb = valid ? b : (B - 1);

    // dt may arrive as int32 or float32 scalar; decode by bit-pattern heuristic.
    float dtf;
    {
        int di = *(const int*)dt_ptr;
        dtf = (di > -16777216 && di < 16777216) ? (float)di : __int_as_float(di);
    }

    // ---- per-slot scalars: lane r owns slot r of its batch ----
    const size_t sb = (size_t)bb * 8 + r;
    const float act0 = act_in[sb];
    const float gate = gate_in[sb];
    const float thr  = thr_in[sb];
    const float rstr = refresh_in[sb];
    const float maint= maint_in[sb];
    const float gsig = gsig_in[sb];
    const float rsig = rsig_in[sb];

    // interference row r (8 floats)
    const float4* ip = (const float4*)(intf + (size_t)bb * 64 + (size_t)r * 8);
    const float4 I0 = ip[0], I1 = ip[1];
    const float Irow[8] = {I0.x, I0.y, I0.z, I0.w, I1.x, I1.y, I1.z, I1.w};

    // inputs: lane r holds elements [r*8, r*8+8)
    const float4* xp = (const float4*)(x_in + (size_t)bb * 64 + (size_t)r * 8);
    const float4 xA = xp[0], xB = xp[1];

    // ---- load memory slots, apply decay ----
    const float4* mp = (const float4*)(mem + (size_t)bb * 512);
    float4 mA[8], mB[8];
#pragma unroll
    for (int s = 0; s < 8; s++) {
        float4 a4 = mp[s * 16 + r * 2];
        float4 b4 = mp[s * 16 + r * 2 + 1];
        a4.x *= 0.95f; a4.y *= 0.95f; a4.z *= 0.95f; a4.w *= 0.95f;
        b4.x *= 0.95f; b4.y *= 0.95f; b4.z *= 0.95f; b4.w *= 0.95f;
        mA[s] = a4; mB[s] = b4;
    }

    // squared norms per slot (all lanes get the full sum)
    float n2[8];
#pragma unroll
    for (int s = 0; s < 8; s++) {
        const float4 a4 = mA[s], b4 = mB[s];
        float p = ((a4.x * a4.x + a4.y * a4.y) + (a4.z * a4.z + a4.w * a4.w))
                + ((b4.x * b4.x + b4.y * b4.y) + (b4.z * b4.z + b4.w * b4.w));
        n2[s] = gsum8(p);
    }

    // ---- activity decay + masks ----
    const float adec = act0 * 0.9f;
    const unsigned actBall = __ballot_sync(FULL, adec > 0.1f);
    const unsigned actMask = (actBall >> (grp * 8)) & 0xffu;
    const unsigned avBall = __ballot_sync(FULL, act0 < 0.2f);
    const unsigned avMask = (avBall >> (grp * 8)) & 0xffu;

    // ---- target slot: argmin with jnp tie-break (lowest index) ----
    const float INF = __int_as_float(0x7f800000);
    float key = avMask ? ((act0 < 0.2f) ? act0 : INF) : act0;
    int idx = r;
#pragma unroll
    for (int off = 1; off < 8; off <<= 1) {
        float ov = __shfl_xor_sync(FULL, key, off);
        int   oi = __shfl_xor_sync(FULL, idx, off);
        if (ov < key || (ov == key && oi < idx)) { key = ov; idx = oi; }
    }
    const int ts = idx;  // uniform within group

    // ---- sequential interference: 56 ordered pair updates ----
#pragma unroll
    for (int i = 0; i < 8; i++) {
#pragma unroll
        for (int j = 0; j < 8; j++) {
            if (i == j) continue;
            const float4 aI = mA[i], bI = mB[i];
            const float4 aJ = mA[j], bJ = mB[j];
            float p = ((aI.x * aJ.x + aI.y * aJ.y) + (aI.z * aJ.z + aI.w * aJ.w))
                    + ((bI.x * bJ.x + bI.y * bJ.y) + (bI.z * bJ.z + bI.w * bJ.w));
            const float dot = gsum8(p);
            // sim = dot / (ni*nj + 1e-6): 1e-6 << ulp(ni*nj~64) -> rsqrt form
            const float sim = dot * rsqrtf(n2[i] * n2[j]);
            const float Iv = __shfl_sync(FULL, Irow[j], i, 8);
            const bool cond = ((actMask >> i) & 1u) && ((actMask >> j) & 1u);
            const float c = cond ? 0.1f * Iv * sim : 0.0f;
            mA[i].x = fmaf(-c, aJ.x, mA[i].x);
            mA[i].y = fmaf(-c, aJ.y, mA[i].y);
            mA[i].z = fmaf(-c, aJ.z, mA[i].z);
            mA[i].w = fmaf(-c, aJ.w, mA[i].w);
            mB[i].x = fmaf(-c, bJ.x, mB[i].x);
            mB[i].y = fmaf(-c, bJ.y, mB[i].y);
            mB[i].z = fmaf(-c, bJ.z, mB[i].z);
            mB[i].w = fmaf(-c, bJ.w, mB[i].w);
            // ||m - c v||^2 = n2 - 2 c dot + c^2 ||v||^2 (incremental, no re-reduce)
            n2[i] = fmaf(c, fmaf(c, n2[j], -2.0f * dot), n2[i]);
        }
    }

    // ---- gating / write ----
    const float gv = 0.7f * gate + 0.3f * __saturatef(gsig);
    const float gs = __shfl_sync(FULL, gv, ts, 8);
    const float th = __shfl_sync(FULL, thr, ts, 8);
    const bool write = gs > th;

    const float in2 = gsum8(((xA.x * xA.x + xA.y * xA.y) + (xA.z * xA.z + xA.w * xA.w))
                          + ((xB.x * xB.x + xB.y * xB.y) + (xB.z * xB.z + xB.w * xB.w)));
    const float inorm = sqrtf(in2);

    float a = adec;
    if (write && r == ts) a = inorm;

    // ---- refresh ----
    const float ru = __saturatef(rsig);
    const float rs = (ru > 0.1f) ? rstr * ru : 0.0f;
    a += rs;

    // ---- maintenance ----
    const float mc = (a > 0.1f)
        ? fmaf(fmaf(0.5f, a, -maint), 0.1f * dtf, maint)
        : maint * 0.95f;

    // ---- capacity limiting: rank active slots ascending (stable ties) ----
    float ab[8];
#pragma unroll
    for (int s = 0; s < 8; s++) ab[s] = __shfl_sync(FULL, a, s, 8);
    const unsigned activeBall = __ballot_sync(FULL, a > 0.1f);
    const unsigned activeMask = (activeBall >> (grp * 8)) & 0xffu;
    const int ndeact = __popc(activeMask) - 4;   // rank<ndeact false if <=0
    int rank = 0;
#pragma unroll
    for (int s = 0; s < 8; s++) {
        const bool sa = (activeMask >> s) & 1u;
        if (sa && (ab[s] < a || (ab[s] == a && s < r))) rank++;
    }
    const bool active_r = (activeMask >> r) & 1u;
    const bool deact = active_r && (rank < ndeact);
    const float afin = deact ? a * 0.5f : a;
    const unsigned deBall = __ballot_sync(FULL, deact);
    const unsigned deMask = (deBall >> (grp * 8)) & 0xffu;

    // broadcast per-slot refresh scales for the m pass
    float rsb[8];
#pragma unroll
    for (int s = 0; s < 8; s++) rsb[s] = __shfl_sync(FULL, rs, s, 8);

    // ---- fused m epilogue: write-blend, refresh scale, deact scale, store ----
    const float wgt = write ? gs * 0.3f : 0.0f;
    if (valid) {
        float4* op = (float4*)(out + (size_t)b * 512);
#pragma unroll
        for (int s = 0; s < 8; s++) {
            const float scale = (1.0f + rsb[s]) * (((deMask >> s) & 1u) ? 0.7f : 1.0f);
            const float take = (s == ts) ? wgt : 0.0f;
            float4 vA = mA[s], vB = mB[s];
            vA.x = (vA.x + take * (xA.x - vA.x)) * scale;
            vA.y = (vA.y + take * (xA.y - vA.y)) * scale;
            vA.z = (vA.z + take * (xA.z - vA.z)) * scale;
            vA.w = (vA.w + take * (xA.w - vA.w)) * scale;
            vB.x = (vB.x + take * (xB.x - vB.x)) * scale;
            vB.y = (vB.y + take * (xB.y - vB.y)) * scale;
            vB.z = (vB.z + take * (xB.z - vB.z)) * scale;
            vB.w = (vB.w + take * (xB.w - vB.w)) * scale;
            op[s * 16 + r * 2]     = vA;
            op[s * 16 + r * 2 + 1] = vB;
        }
    }

    // ---- per-batch reductions + scalar outputs ----
    const float tot  = gsum8(afin);
    const float msum = gsum8(mc);
    const unsigned loadBall = __ballot_sync(FULL, afin > 0.1f);
    const int mload = __popc((loadBall >> (grp * 8)) & 0xffu);

    const size_t OA  = (size_t)B * 512;      // m size
    const size_t SB8 = (size_t)B * 8;
    if (valid) {
        out[OA + (size_t)b * 8 + r]           = afin;  // a
        out[OA + SB8 + (size_t)b * 8 + r]     = gv;    // g
        out[OA + 2 * SB8 + (size_t)b * 8 + r] = mc;    // mc
        if (r == 0) {
            out[OA + 3 * SB8 + (size_t)b]                 = (float)mload;
            out[OA + 3 * SB8 + (size_t)B + (size_t)b]     = tot;
            out[OA + 3 * SB8 + 2 * (size_t)B + (size_t)b] = msum * 0.125f;
        }
    }
}

extern "C" void kernel_launch(void* const* d_in, const int* in_sizes, int n_in,
                              void* d_out, int out_size)
{
    const int B = in_sizes[0] / 512;   // B*S*D / (8*64)
    const int threads = 256;           // 8 warps * 4 batches = 32 batches/block
    const int batchesPerBlock = 32;
    const int grid = (B + batchesPerBlock - 1) / batchesPerBlock;
    wm_kernel<<<grid, threads>>>(
        (const float*)d_in[0], (const float*)d_in[1], (const float*)d_in[2],
        (const float*)d_in[3], (const float*)d_in[4], (const float*)d_in[5],
        (const float*)d_in[6], (const float*)d_in[7], (const float*)d_in[8],
        (const float*)d_in[9], (const void*)d_in[10],
        (float*)d_out, B);
}